// round 2
// baseline (speedup 1.0000x reference)
#include <cuda_runtime.h>

// VectorQuantizer: z [32,4096,64] fp32, W [512,64] fp32.
// Outputs concatenated fp32: z_q_st (8388608) | indices-as-float (131072) | loss (1).
//
// R2: fp32x2 packed FMA (2 codes per 64-bit lane pair; each code keeps its own
// sequential ascending-k fma.rn chain -> bitwise identical to R1), wsq fused
// into the main kernel (kills the 19.8us grid=1 launch).

#define DIM      64
#define KCODES   512
#define NROWS    131072              // 32*4096
#define THREADS  256
#define GRID     (NROWS / THREADS)   // 512
#define NELEM_ZQ (NROWS * DIM)       // 8388608
#define NPAIR    (KCODES / 2)        // 256 code pairs

__device__ double g_part[GRID];

typedef unsigned long long u64;

__device__ __forceinline__ u64 pack_dup(float x) {
    u64 r;
    asm("mov.b64 %0, {%1, %1};" : "=l"(r) : "f"(x));
    return r;
}
__device__ __forceinline__ void unpack2(u64 v, float& lo, float& hi) {
    asm("mov.b64 {%0, %1}, %2;" : "=f"(lo), "=f"(hi) : "l"(v));
}
__device__ __forceinline__ void ffma2(u64& acc, u64 a, u64 b) {
    // two independent IEEE fma.rn lanes: lane0 = code 2p, lane1 = code 2p+1
    asm("fma.rn.f32x2 %0, %1, %2, %0;" : "+l"(acc) : "l"(a), "l"(b));
}

// ---------------------------------------------------------------------------
// Main: one thread per row. W staged in shared, pre-interleaved for f32x2:
//   sW4[p*32 + kk] = { W[2p][2kk], W[2p+1][2kk], W[2p][2kk+1], W[2p+1][2kk+1] }
// All distance math reproduces the reference rounding exactly:
//   zz, wsq: fmul_rn then sequential fadd_rn, ascending k
//   dot:     sequential ascending-k fma.rn per code
//   dist = fsub_rn(fadd_rn(zz, wsq), fmul_rn(2, dot)); strict < argmin.
// ---------------------------------------------------------------------------
__global__ __launch_bounds__(THREADS, 1)
void vq_kernel(const float* __restrict__ z,
               const float* __restrict__ W,
               float* __restrict__ out,
               int out_size) {
    extern __shared__ float smem[];                  // 128KB packed W + 2KB wsq
    float* sWf  = smem;                              // packed W as floats
    float* swsq = smem + KCODES * DIM;

    // ---- stage W into smem, interleaved (code-pair, k-pair) ----
    for (int idx = threadIdx.x; idx < KCODES * (DIM / 2); idx += THREADS) {
        int j  = idx >> 5;          // code 0..511
        int kk = idx & 31;          // k-pair 0..31
        float2 g = ((const float2*)W)[idx];          // {W[j][2kk], W[j][2kk+1]}
        int base = ((j >> 1) * 32 + kk) * 4 + (j & 1);
        sWf[base]     = g.x;        // k = 2kk
        sWf[base + 2] = g.y;        // k = 2kk+1
    }
    // ---- fused wsq (sequential rounded-square sum, ascending k) ----
    for (int j = threadIdx.x; j < KCODES; j += THREADS) {
        const float* w = W + j * DIM;
        float acc = 0.0f;
        #pragma unroll
        for (int k = 0; k < DIM; k++)
            acc = __fadd_rn(acc, __fmul_rn(w[k], w[k]));
        swsq[j] = acc;
    }
    __syncthreads();

    const int row = blockIdx.x * THREADS + threadIdx.x;
    const float* zr = z + (size_t)row * DIM;

    // ---- z row: compute zz, then keep only the packed duplicate form ----
    u64  zp[DIM];
    float zz = 0.0f;
    #pragma unroll
    for (int k = 0; k < DIM; k += 4) {
        float4 v = *(const float4*)(zr + k);
        zz = __fadd_rn(zz, __fmul_rn(v.x, v.x));
        zz = __fadd_rn(zz, __fmul_rn(v.y, v.y));
        zz = __fadd_rn(zz, __fmul_rn(v.z, v.z));
        zz = __fadd_rn(zz, __fmul_rn(v.w, v.w));
        zp[k]   = pack_dup(v.x);
        zp[k+1] = pack_dup(v.y);
        zp[k+2] = pack_dup(v.z);
        zp[k+3] = pack_dup(v.w);
    }

    float bestDist = 3.0e38f;
    int   bestIdx  = 0;

    const ulonglong2* sWp = (const ulonglong2*)sWf;  // [p*32 + kk] -> {pair@2kk, pair@2kk+1}

    // 8 codes (4 pairs) at a time; 4 independent FFMA2 chains hide latency
    #pragma unroll 1
    for (int p0 = 0; p0 < NPAIR; p0 += 4) {
        u64 acc0 = 0ull, acc1 = 0ull, acc2 = 0ull, acc3 = 0ull;

        #pragma unroll
        for (int kk = 0; kk < 32; kk++) {
            ulonglong2 w0 = sWp[(p0 + 0) * 32 + kk];
            ulonglong2 w1 = sWp[(p0 + 1) * 32 + kk];
            ulonglong2 w2 = sWp[(p0 + 2) * 32 + kk];
            ulonglong2 w3 = sWp[(p0 + 3) * 32 + kk];
            u64 ze = zp[2 * kk];
            u64 zo = zp[2 * kk + 1];
            ffma2(acc0, ze, w0.x);  ffma2(acc0, zo, w0.y);
            ffma2(acc1, ze, w1.x);  ffma2(acc1, zo, w1.y);
            ffma2(acc2, ze, w2.x);  ffma2(acc2, zo, w2.y);
            ffma2(acc3, ze, w3.x);  ffma2(acc3, zo, w3.y);
        }

        // compare in ascending-j order; strict < keeps first occurrence
        float d0, d1;
        u64 accs[4] = {acc0, acc1, acc2, acc3};
        #pragma unroll
        for (int q = 0; q < 4; q++) {
            unpack2(accs[q], d0, d1);
            int j = (p0 + q) * 2;
            float s  = __fadd_rn(zz, swsq[j]);
            float de = __fsub_rn(s, __fmul_rn(2.0f, d0));
            if (de < bestDist) { bestDist = de; bestIdx = j; }
            s  = __fadd_rn(zz, swsq[j + 1]);
            de = __fsub_rn(s, __fmul_rn(2.0f, d1));
            if (de < bestDist) { bestDist = de; bestIdx = j + 1; }
        }
    }

    // ---- epilogue: z_q_st = fl(z + fl(w - z)); loss term fl(z - z_q_st)^2 ----
    float lsum = 0.0f;
    const int pb = bestIdx >> 1, lb = bestIdx & 1;
    #pragma unroll
    for (int k = 0; k < DIM; k += 2) {
        float z0, zdup;
        float w0 = sWf[(pb * 32 + (k >> 1)) * 4 + lb];        // W[best][k]
        float w1 = sWf[(pb * 32 + (k >> 1)) * 4 + 2 + lb];    // W[best][k+1]
        unpack2(zp[k], z0, zdup);
        float st0 = __fadd_rn(z0, __fsub_rn(w0, z0));
        float df0 = __fsub_rn(z0, st0);
        lsum = __fadd_rn(lsum, __fmul_rn(df0, df0));
        unpack2(zp[k + 1], z0, zdup);
        float st1 = __fadd_rn(z0, __fsub_rn(w1, z0));
        float df1 = __fsub_rn(z0, st1);
        lsum = __fadd_rn(lsum, __fmul_rn(df1, df1));
        *(float2*)(out + (size_t)row * DIM + k) = make_float2(st0, st1);
    }

    // indices (as float) after z_q block
    if (out_size > NELEM_ZQ + row)
        out[NELEM_ZQ + row] = (float)bestIdx;

    // deterministic block-level loss reduction
    __shared__ double red[THREADS];
    red[threadIdx.x] = (double)lsum;
    __syncthreads();
    #pragma unroll
    for (int s = THREADS / 2; s > 0; s >>= 1) {
        if (threadIdx.x < s) red[threadIdx.x] += red[threadIdx.x + s];
        __syncthreads();
    }
    if (threadIdx.x == 0) g_part[blockIdx.x] = red[0];
}

// ---------------------------------------------------------------------------
// Final loss: sequential deterministic sum of 512 block partials
// ---------------------------------------------------------------------------
__global__ void loss_kernel(float* __restrict__ out, int out_size) {
    if (threadIdx.x == 0 && blockIdx.x == 0) {
        double t = 0.0;
        for (int i = 0; i < GRID; i++) t += g_part[i];
        float loss = (float)(0.25 * t / (double)((size_t)NROWS * DIM));
        int loss_pos = NELEM_ZQ + NROWS;
        if (out_size > loss_pos) out[loss_pos] = loss;
    }
}

extern "C" void kernel_launch(void* const* d_in, const int* in_sizes, int n_in,
                              void* d_out, int out_size) {
    const float* z = (const float*)d_in[0];
    const float* W = (const float*)d_in[1];
    float* out = (float*)d_out;

    size_t smem = (size_t)(KCODES * DIM + KCODES) * sizeof(float);
    static bool attr_set = false;
    if (!attr_set) {
        cudaFuncSetAttribute(vq_kernel, cudaFuncAttributeMaxDynamicSharedMemorySize,
                             (int)smem);
        attr_set = true;
    }

    vq_kernel<<<GRID, THREADS, smem>>>(z, W, out, out_size);
    loss_kernel<<<1, 32>>>(out, out_size);
}

// round 3
// speedup vs baseline: 1.0514x; 1.0514x over previous
#include <cuda_runtime.h>

// VectorQuantizer: z [32,4096,64] fp32, W [512,64] fp32.
// Outputs concatenated fp32: z_q_st (8388608) | indices-as-float (131072) | loss (1).
//
// R3: FFMA2 retained, but z kept as 64 plain floats (64 regs, not 128);
// the duplicated {z_k, z_k} operand is rebuilt per k-pair with mov.b64
// (2 MOVs per 8 FFMA2). Discriminates register-pressure vs FFMA2-rate as
// the cause of R2's regression. loss_kernel parallelized (was 27.5us serial).

#define DIM      64
#define KCODES   512
#define NROWS    131072              // 32*4096
#define THREADS  256
#define GRID     (NROWS / THREADS)   // 512
#define NELEM_ZQ (NROWS * DIM)       // 8388608
#define NPAIR    (KCODES / 2)        // 256 code pairs

__device__ double g_part[GRID];

typedef unsigned long long u64;

__device__ __forceinline__ u64 pack_dup(float x) {
    u64 r;
    asm("mov.b64 %0, {%1, %1};" : "=l"(r) : "f"(x));
    return r;
}
__device__ __forceinline__ void unpack2(u64 v, float& lo, float& hi) {
    asm("mov.b64 {%0, %1}, %2;" : "=f"(lo), "=f"(hi) : "l"(v));
}
__device__ __forceinline__ void ffma2(u64& acc, u64 a, u64 b) {
    // two independent IEEE fma.rn lanes: lane0 = code 2p, lane1 = code 2p+1
    asm("fma.rn.f32x2 %0, %1, %2, %0;" : "+l"(acc) : "l"(a), "l"(b));
}

// ---------------------------------------------------------------------------
// Main: one thread per row. W staged in shared, pre-interleaved for f32x2:
//   sWp[p*32+kk] = { {W[2p][2kk],W[2p+1][2kk]}, {W[2p][2kk+1],W[2p+1][2kk+1]} }
// All distance math reproduces the reference rounding exactly (verified
// rel_err==0.0 in R1/R2):
//   zz, wsq: fmul_rn then sequential fadd_rn, ascending k
//   dot:     sequential ascending-k fma.rn per code (per f32x2 lane)
//   dist = fsub_rn(fadd_rn(zz, wsq), fmul_rn(2, dot)); strict < argmin.
// ---------------------------------------------------------------------------
__global__ __launch_bounds__(THREADS, 1)
void vq_kernel(const float* __restrict__ z,
               const float* __restrict__ W,
               float* __restrict__ out,
               int out_size) {
    extern __shared__ float smem[];                  // 128KB packed W + 2KB wsq
    float* sWf  = smem;                              // packed W as floats
    float* swsq = smem + KCODES * DIM;

    // ---- stage W into smem, interleaved (code-pair, k-pair) ----
    for (int idx = threadIdx.x; idx < KCODES * (DIM / 2); idx += THREADS) {
        int j  = idx >> 5;          // code 0..511
        int kk = idx & 31;          // k-pair 0..31
        float2 g = ((const float2*)W)[idx];          // {W[j][2kk], W[j][2kk+1]}
        int base = ((j >> 1) * 32 + kk) * 4 + (j & 1);
        sWf[base]     = g.x;        // k = 2kk
        sWf[base + 2] = g.y;        // k = 2kk+1
    }
    // ---- fused wsq (sequential rounded-square sum, ascending k) ----
    for (int j = threadIdx.x; j < KCODES; j += THREADS) {
        const float* w = W + j * DIM;
        float acc = 0.0f;
        #pragma unroll
        for (int k = 0; k < DIM; k++)
            acc = __fadd_rn(acc, __fmul_rn(w[k], w[k]));
        swsq[j] = acc;
    }
    __syncthreads();

    const int row = blockIdx.x * THREADS + threadIdx.x;
    const float* zr = z + (size_t)row * DIM;

    // ---- z row as plain floats (64 regs), zz sequential ----
    float zv[DIM];
    float zz = 0.0f;
    #pragma unroll
    for (int k = 0; k < DIM; k += 4) {
        float4 v = *(const float4*)(zr + k);
        zv[k] = v.x; zv[k+1] = v.y; zv[k+2] = v.z; zv[k+3] = v.w;
    }
    #pragma unroll
    for (int k = 0; k < DIM; k++)
        zz = __fadd_rn(zz, __fmul_rn(zv[k], zv[k]));

    float bestDist = 3.0e38f;
    int   bestIdx  = 0;

    const ulonglong2* sWp = (const ulonglong2*)sWf;

    // 8 codes (4 pairs) at a time; dup-z built on the fly (2 MOVs / 8 FFMA2)
    #pragma unroll 1
    for (int p0 = 0; p0 < NPAIR; p0 += 4) {
        u64 acc0 = 0ull, acc1 = 0ull, acc2 = 0ull, acc3 = 0ull;
        const ulonglong2* w0p = sWp + (p0 + 0) * 32;
        const ulonglong2* w1p = sWp + (p0 + 1) * 32;
        const ulonglong2* w2p = sWp + (p0 + 2) * 32;
        const ulonglong2* w3p = sWp + (p0 + 3) * 32;

        #pragma unroll
        for (int kk = 0; kk < 32; kk++) {
            ulonglong2 w0 = w0p[kk];
            ulonglong2 w1 = w1p[kk];
            ulonglong2 w2 = w2p[kk];
            ulonglong2 w3 = w3p[kk];
            u64 ze = pack_dup(zv[2 * kk]);
            u64 zo = pack_dup(zv[2 * kk + 1]);
            ffma2(acc0, ze, w0.x);  ffma2(acc0, zo, w0.y);
            ffma2(acc1, ze, w1.x);  ffma2(acc1, zo, w1.y);
            ffma2(acc2, ze, w2.x);  ffma2(acc2, zo, w2.y);
            ffma2(acc3, ze, w3.x);  ffma2(acc3, zo, w3.y);
        }

        // compare in ascending-j order; strict < keeps first occurrence
        float d0, d1;
        u64 accs[4] = {acc0, acc1, acc2, acc3};
        #pragma unroll
        for (int q = 0; q < 4; q++) {
            unpack2(accs[q], d0, d1);
            int j = (p0 + q) * 2;
            float s  = __fadd_rn(zz, swsq[j]);
            float de = __fsub_rn(s, __fmul_rn(2.0f, d0));
            if (de < bestDist) { bestDist = de; bestIdx = j; }
            s  = __fadd_rn(zz, swsq[j + 1]);
            de = __fsub_rn(s, __fmul_rn(2.0f, d1));
            if (de < bestDist) { bestDist = de; bestIdx = j + 1; }
        }
    }

    // ---- epilogue: z_q_st = fl(z + fl(w - z)); loss term fl(z - z_q_st)^2 ----
    float lsum = 0.0f;
    const int pb = bestIdx >> 1, lb = bestIdx & 1;
    #pragma unroll
    for (int k = 0; k < DIM; k += 2) {
        float w0 = sWf[(pb * 32 + (k >> 1)) * 4 + lb];        // W[best][k]
        float w1 = sWf[(pb * 32 + (k >> 1)) * 4 + 2 + lb];    // W[best][k+1]
        float st0 = __fadd_rn(zv[k],     __fsub_rn(w0, zv[k]));
        float df0 = __fsub_rn(zv[k],     st0);
        lsum = __fadd_rn(lsum, __fmul_rn(df0, df0));
        float st1 = __fadd_rn(zv[k + 1], __fsub_rn(w1, zv[k + 1]));
        float df1 = __fsub_rn(zv[k + 1], st1);
        lsum = __fadd_rn(lsum, __fmul_rn(df1, df1));
        *(float2*)(out + (size_t)row * DIM + k) = make_float2(st0, st1);
    }

    // indices (as float) after z_q block
    if (out_size > NELEM_ZQ + row)
        out[NELEM_ZQ + row] = (float)bestIdx;

    // deterministic block-level loss reduction
    __shared__ double red[THREADS];
    red[threadIdx.x] = (double)lsum;
    __syncthreads();
    #pragma unroll
    for (int s = THREADS / 2; s > 0; s >>= 1) {
        if (threadIdx.x < s) red[threadIdx.x] += red[threadIdx.x + s];
        __syncthreads();
    }
    if (threadIdx.x == 0) g_part[blockIdx.x] = red[0];
}

// ---------------------------------------------------------------------------
// Final loss: parallel deterministic tree reduction of 512 block partials
// (fixed pairing -> deterministic; was a 27.5us serial loop in R2)
// ---------------------------------------------------------------------------
__global__ void loss_kernel(float* __restrict__ out, int out_size) {
    __shared__ double red[GRID];
    red[threadIdx.x] = g_part[threadIdx.x];
    __syncthreads();
    #pragma unroll
    for (int s = GRID / 2; s > 0; s >>= 1) {
        if (threadIdx.x < s) red[threadIdx.x] += red[threadIdx.x + s];
        __syncthreads();
    }
    if (threadIdx.x == 0) {
        float loss = (float)(0.25 * red[0] / (double)((size_t)NROWS * DIM));
        int loss_pos = NELEM_ZQ + NROWS;
        if (out_size > loss_pos) out[loss_pos] = loss;
    }
}

extern "C" void kernel_launch(void* const* d_in, const int* in_sizes, int n_in,
                              void* d_out, int out_size) {
    const float* z = (const float*)d_in[0];
    const float* W = (const float*)d_in[1];
    float* out = (float*)d_out;

    size_t smem = (size_t)(KCODES * DIM + KCODES) * sizeof(float);
    static bool attr_set = false;
    if (!attr_set) {
        cudaFuncSetAttribute(vq_kernel, cudaFuncAttributeMaxDynamicSharedMemorySize,
                             (int)smem);
        attr_set = true;
    }

    vq_kernel<<<GRID, THREADS, smem>>>(z, W, out, out_size);
    loss_kernel<<<1, GRID>>>(out, out_size);
}

// round 4
// speedup vs baseline: 1.8636x; 1.7725x over previous
#include <cuda_runtime.h>
#include <cuda_bf16.h>

// VectorQuantizer: z [32,4096,64] fp32, W [512,64] fp32.
// Out fp32: z_q_st (8388608) | indices-as-float (131072) | loss (1).
//
// R4: bf16 mma.sync tensor-core filter + rigorous-margin exact fp32 rescore.
// Filter error bound (Cauchy-Schwarz + bf16-rne rounding) guarantees the true
// argmin is in the candidate set; candidates rescored with the bitwise-exact
// reference chain (verified rel_err==0.0 in R1-R3).

#define DIM       64
#define KCODES    512
#define NROWS     131072
#define ROWS_CTA  128
#define GRIDM     (NROWS / ROWS_CTA)     // 1024
#define THREADS   256
#define NELEM_ZQ  (NROWS * DIM)

#define SZ_STRIDE 66     // fp32 z row stride (words), even for float2 align
#define SW_STRIDE 36     // W bf16-pair row stride (words): conflict-free B-frag

__device__ float        g_wsq[KCODES];
__device__ float        g_wmax;
__device__ unsigned int g_Wbf[KCODES * (DIM / 2)];
__device__ double       g_part[GRIDM];

// monotone float<->uint order-preserving encode (handles negatives)
__device__ __forceinline__ unsigned int fflip(float x) {
    unsigned int u = __float_as_uint(x);
    return (u & 0x80000000u) ? ~u : (u | 0x80000000u);
}
__device__ __forceinline__ float funflip(unsigned int u) {
    return (u & 0x80000000u) ? __uint_as_float(u ^ 0x80000000u)
                             : __uint_as_float(~u);
}

// ---------------------------------------------------------------------------
// Prologue: exact wsq (sequential chain), W -> bf16 (rne), wmax = max ||w_j||
// ---------------------------------------------------------------------------
__global__ void prep_kernel(const float* __restrict__ W) {
    int j = threadIdx.x;                   // 512 threads
    const float* w = W + j * DIM;
    float acc = 0.0f;
    #pragma unroll
    for (int k = 0; k < DIM; k++)
        acc = __fadd_rn(acc, __fmul_rn(w[k], w[k]));
    g_wsq[j] = acc;
    #pragma unroll
    for (int k = 0; k < DIM; k += 2) {
        float2 v = *(const float2*)(w + k);
        __nv_bfloat162 b = __float22bfloat162_rn(v);   // lo=v.x, hi=v.y
        g_Wbf[j * (DIM / 2) + (k >> 1)] = *(unsigned int*)&b;
    }
    __shared__ float red[512];
    red[j] = sqrtf(acc);
    __syncthreads();
    #pragma unroll
    for (int s = 256; s > 0; s >>= 1) {
        if (j < s) red[j] = fmaxf(red[j], red[j + s]);
        __syncthreads();
    }
    if (j == 0) g_wmax = red[0];
}

// ---------------------------------------------------------------------------
// Main kernel
// ---------------------------------------------------------------------------
__global__ __launch_bounds__(THREADS, 2)
void vq_main(const float* __restrict__ z, const float* __restrict__ W,
             float* __restrict__ out, int out_size) {
    extern __shared__ char smraw[];
    unsigned long long* sbest = (unsigned long long*)smraw;              // 128
    double*       sred = (double*)(smraw + 1024);                        // 256
    float*        sz   = (float*)(smraw + 3072);                         // 128*66
    unsigned int* sW   = (unsigned int*)(smraw + 3072 + ROWS_CTA*SZ_STRIDE*4);
    float*        swsq = (float*)((char*)sW + KCODES*SW_STRIDE*4);       // 512
    unsigned int* srmin = (unsigned int*)(swsq + KCODES);                // 128
    float*        sthr  = (float*)(srmin + ROWS_CTA);                    // 128
    float*        szz   = (float*)(sthr + ROWS_CTA);                     // 128

    const int tid  = threadIdx.x;
    const int lane = tid & 31;
    const int wid  = tid >> 5;
    const int gid  = lane >> 2;          // group id (row within tile)
    const int tig  = lane & 3;           // thread in group
    const int rowbase = blockIdx.x * ROWS_CTA;

    // ---- stage z fp32 (coalesced float2) ----
    const float2* zg = (const float2*)(z + (size_t)rowbase * DIM);
    for (int i = tid; i < ROWS_CTA * (DIM / 2); i += THREADS) {
        int r = i >> 5, c2 = i & 31;
        *(float2*)(sz + r * SZ_STRIDE + c2 * 2) = zg[i];
    }
    // ---- stage W bf16 pairs into padded smem ----
    for (int i = tid; i < KCODES * (DIM / 2); i += THREADS) {
        int j = i >> 5, kw = i & 31;
        sW[j * SW_STRIDE + kw] = g_Wbf[i];
    }
    for (int i = tid; i < KCODES; i += THREADS) swsq[i] = g_wsq[i];
    for (int i = tid; i < ROWS_CTA; i += THREADS) {
        srmin[i] = 0xFFFFFFFFu;
        sbest[i] = 0xFFFFFFFFFFFFFFFFull;
    }
    __syncthreads();

    // ---- A fragments (rows m0, m0+8), bf16-converted once, kept in regs ----
    const int m0 = wid * 16 + gid;
    unsigned int A[4][4];
    #pragma unroll
    for (int kk = 0; kk < 4; kk++) {
        int kb = kk * 16;
        float2 p0 = *(float2*)(sz + m0 * SZ_STRIDE + kb + tig * 2);
        float2 p1 = *(float2*)(sz + (m0 + 8) * SZ_STRIDE + kb + tig * 2);
        float2 p2 = *(float2*)(sz + m0 * SZ_STRIDE + kb + 8 + tig * 2);
        float2 p3 = *(float2*)(sz + (m0 + 8) * SZ_STRIDE + kb + 8 + tig * 2);
        __nv_bfloat162 b;
        b = __float22bfloat162_rn(p0); A[kk][0] = *(unsigned int*)&b;
        b = __float22bfloat162_rn(p1); A[kk][1] = *(unsigned int*)&b;
        b = __float22bfloat162_rn(p2); A[kk][2] = *(unsigned int*)&b;
        b = __float22bfloat162_rn(p3); A[kk][3] = *(unsigned int*)&b;
    }

    // ================= PASS 1: per-row filter minimum =================
    {
        float rmin0 = 3.0e38f, rmin1 = 3.0e38f;
        #pragma unroll 1
        for (int n0 = 0; n0 < KCODES / 8; n0++) {
            const int j0 = n0 * 8;
            float c0 = 0.f, c1 = 0.f, c2 = 0.f, c3 = 0.f;
            const unsigned int* wrow = sW + (j0 + gid) * SW_STRIDE + tig;
            #pragma unroll
            for (int kk = 0; kk < 4; kk++) {
                unsigned int b0 = wrow[kk * 8];
                unsigned int b1 = wrow[kk * 8 + 4];
                asm volatile(
                    "mma.sync.aligned.m16n8k16.row.col.f32.bf16.bf16.f32 "
                    "{%0,%1,%2,%3}, {%4,%5,%6,%7}, {%8,%9}, {%0,%1,%2,%3};"
                    : "+f"(c0), "+f"(c1), "+f"(c2), "+f"(c3)
                    : "r"(A[kk][0]), "r"(A[kk][1]), "r"(A[kk][2]), "r"(A[kk][3]),
                      "r"(b0), "r"(b1));
            }
            const int jc = j0 + tig * 2;
            float w0 = swsq[jc], w1 = swsq[jc + 1];
            float s0 = __fsub_rn(w0, __fmul_rn(2.0f, c0));
            float s1 = __fsub_rn(w1, __fmul_rn(2.0f, c1));
            float s2 = __fsub_rn(w0, __fmul_rn(2.0f, c2));
            float s3 = __fsub_rn(w1, __fmul_rn(2.0f, c3));
            rmin0 = fminf(rmin0, fminf(s0, s1));
            rmin1 = fminf(rmin1, fminf(s2, s3));
        }
        atomicMin(&srmin[m0], fflip(rmin0));
        atomicMin(&srmin[m0 + 8], fflip(rmin1));
    }
    __syncthreads();

    // ---- exact zz per row + rigorous threshold ----
    if (tid < ROWS_CTA) {
        const float* zr = sz + tid * SZ_STRIDE;
        float acc = 0.0f;
        #pragma unroll
        for (int k = 0; k < DIM; k++)
            acc = __fadd_rn(acc, __fmul_rn(zr[k], zr[k]));
        szz[tid] = acc;
        // width = 2*delta, delta = 2*(2^-8*1.05)*||z||*wmax + dist-rounding slack
        float width = 0.0164f * sqrtf(acc) * g_wmax + 5e-5f;
        sthr[tid] = funflip(srmin[tid]) + width;
    }
    __syncthreads();

    // ================= PASS 2: candidates + exact rescore =================
    {
        const float thr_a = sthr[m0];
        const float thr_b = sthr[m0 + 8];
        #pragma unroll 1
        for (int n0 = 0; n0 < KCODES / 8; n0++) {
            const int j0 = n0 * 8;
            float c0 = 0.f, c1 = 0.f, c2 = 0.f, c3 = 0.f;
            const unsigned int* wrow = sW + (j0 + gid) * SW_STRIDE + tig;
            #pragma unroll
            for (int kk = 0; kk < 4; kk++) {
                unsigned int b0 = wrow[kk * 8];
                unsigned int b1 = wrow[kk * 8 + 4];
                asm volatile(
                    "mma.sync.aligned.m16n8k16.row.col.f32.bf16.bf16.f32 "
                    "{%0,%1,%2,%3}, {%4,%5,%6,%7}, {%8,%9}, {%0,%1,%2,%3};"
                    : "+f"(c0), "+f"(c1), "+f"(c2), "+f"(c3)
                    : "r"(A[kk][0]), "r"(A[kk][1]), "r"(A[kk][2]), "r"(A[kk][3]),
                      "r"(b0), "r"(b1));
            }
            const int jc = j0 + tig * 2;
            float w0 = swsq[jc], w1 = swsq[jc + 1];
            float s0 = __fsub_rn(w0, __fmul_rn(2.0f, c0));
            float s1 = __fsub_rn(w1, __fmul_rn(2.0f, c1));
            float s2 = __fsub_rn(w0, __fmul_rn(2.0f, c2));
            float s3 = __fsub_rn(w1, __fmul_rn(2.0f, c3));

            #pragma unroll
            for (int q = 0; q < 4; q++) {
                float s    = (q == 0) ? s0 : (q == 1) ? s1 : (q == 2) ? s2 : s3;
                float thr  = (q < 2) ? thr_a : thr_b;
                int   r    = (q < 2) ? m0 : m0 + 8;
                int   j    = jc + (q & 1);
                if (s <= thr) {
                    // exact rescore: bitwise reference chain
                    const float* zr = sz + r * SZ_STRIDE;
                    const float* wr = W + j * DIM;
                    float acc = 0.0f;
                    #pragma unroll
                    for (int k = 0; k < DIM; k++)
                        acc = __fmaf_rn(zr[k], wr[k], acc);
                    float dist = __fsub_rn(__fadd_rn(szz[r], swsq[j]),
                                           __fmul_rn(2.0f, acc));
                    unsigned long long pk =
                        ((unsigned long long)fflip(dist) << 32) | (unsigned int)j;
                    atomicMin(&sbest[r], pk);   // lexicographic (dist, j)
                }
            }
        }
    }
    __syncthreads();

    // ================= epilogue: z_q_st, indices, loss =================
    float lsum = 0.0f;
    if (tid < ROWS_CTA) {
        const int r = tid;
        const int grow = rowbase + r;
        const int bj = (int)(sbest[r] & 0xFFFFFFFFull);
        const float* zr = sz + r * SZ_STRIDE;
        const float* wr = W + bj * DIM;
        #pragma unroll
        for (int k = 0; k < DIM; k += 4) {
            float4 wv = *(const float4*)(wr + k);
            float4 o;
            float df;
            o.x = __fadd_rn(zr[k],     __fsub_rn(wv.x, zr[k]));
            df  = __fsub_rn(zr[k],     o.x); lsum = __fadd_rn(lsum, __fmul_rn(df, df));
            o.y = __fadd_rn(zr[k + 1], __fsub_rn(wv.y, zr[k + 1]));
            df  = __fsub_rn(zr[k + 1], o.y); lsum = __fadd_rn(lsum, __fmul_rn(df, df));
            o.z = __fadd_rn(zr[k + 2], __fsub_rn(wv.z, zr[k + 2]));
            df  = __fsub_rn(zr[k + 2], o.z); lsum = __fadd_rn(lsum, __fmul_rn(df, df));
            o.w = __fadd_rn(zr[k + 3], __fsub_rn(wv.w, zr[k + 3]));
            df  = __fsub_rn(zr[k + 3], o.w); lsum = __fadd_rn(lsum, __fmul_rn(df, df));
            *(float4*)(out + (size_t)grow * DIM + k) = o;
        }
        if (out_size > NELEM_ZQ + grow)
            out[NELEM_ZQ + grow] = (float)bj;
    }
    sred[tid] = (double)lsum;
    __syncthreads();
    #pragma unroll
    for (int s = THREADS / 2; s > 0; s >>= 1) {
        if (tid < s) sred[tid] += sred[tid + s];
        __syncthreads();
    }
    if (tid == 0) g_part[blockIdx.x] = sred[0];
}

// ---------------------------------------------------------------------------
// Final loss: deterministic tree over 1024 block partials
// ---------------------------------------------------------------------------
__global__ void loss_kernel(float* __restrict__ out, int out_size) {
    __shared__ double red[GRIDM];
    red[threadIdx.x] = g_part[threadIdx.x];
    __syncthreads();
    #pragma unroll
    for (int s = GRIDM / 2; s > 0; s >>= 1) {
        if (threadIdx.x < s) red[threadIdx.x] += red[threadIdx.x + s];
        __syncthreads();
    }
    if (threadIdx.x == 0) {
        float loss = (float)(0.25 * red[0] / (double)((size_t)NROWS * DIM));
        int loss_pos = NELEM_ZQ + NROWS;
        if (out_size > loss_pos) out[loss_pos] = loss;
    }
}

extern "C" void kernel_launch(void* const* d_in, const int* in_sizes, int n_in,
                              void* d_out, int out_size) {
    const float* z = (const float*)d_in[0];
    const float* W = (const float*)d_in[1];
    float* out = (float*)d_out;

    size_t smem = 3072
                + (size_t)ROWS_CTA * SZ_STRIDE * 4     // z fp32
                + (size_t)KCODES * SW_STRIDE * 4       // W bf16 padded
                + KCODES * 4                           // wsq
                + ROWS_CTA * 4 * 3;                    // rmin, thr, zz
    static bool attr_set = false;
    if (!attr_set) {
        cudaFuncSetAttribute(vq_main, cudaFuncAttributeMaxDynamicSharedMemorySize,
                             (int)smem);
        attr_set = true;
    }

    prep_kernel<<<1, KCODES>>>(W);
    vq_main<<<GRIDM, THREADS, smem>>>(z, W, out, out_size);
    loss_kernel<<<1, GRIDM>>>(out, out_size);
}